// round 4
// baseline (speedup 1.0000x reference)
#include <cuda_runtime.h>
#include <cuda_bf16.h>
#include <cstdint>
#include <cstddef>

// Problem constants
#define BB 2
#define LL 2048
#define EE 2048
#define HQ 16
#define HKV 2
#define DD 128
#define MROWS (BB*LL)   // 4096

// Scratch (device globals — no allocations allowed)
__device__ float g_q[(size_t)MROWS * HQ * DD];     // 32 MB
__device__ float g_k[(size_t)MROWS * HKV * DD];    // 4 MB
__device__ float g_v[(size_t)MROWS * HKV * DD];    // 4 MB
__device__ float g_attn[(size_t)MROWS * HQ * DD];  // 32 MB

// ---------------------------------------------------------------------------
// SGEMM: C[M,N] = A[M,K] @ W[K,N] (+ bias). Row-major. M%128==0, N%128==0,
// K%16==0 (all hold here). 256 threads, 128x128 tile, 8x8 per-thread.
// ---------------------------------------------------------------------------
__global__ __launch_bounds__(256) void sgemm_bias(
    const float* __restrict__ A, const float* __restrict__ Wm,
    const float* __restrict__ bias, float* __restrict__ C,
    int M, int N, int K)
{
    __shared__ float As[16][132];   // A tile, transposed: As[k][m]
    __shared__ float Bs[16][128];   // W tile: Bs[k][n]

    const int t  = threadIdx.x;
    const int ty = t >> 4;          // 0..15
    const int tx = t & 15;          // 0..15
    const int bm = blockIdx.y * 128;
    const int bn = blockIdx.x * 128;

    float acc[8][8];
#pragma unroll
    for (int i = 0; i < 8; i++)
#pragma unroll
        for (int j = 0; j < 8; j++) acc[i][j] = 0.f;

    for (int k0 = 0; k0 < K; k0 += 16) {
#pragma unroll
        for (int i = 0; i < 2; i++) {
            int idx = t + i * 256;              // 0..511
            // A: 128 rows x 16 cols -> 512 float4
            int ra = idx >> 2;                  // row 0..127
            int ca = (idx & 3) << 2;            // col 0,4,8,12
            float4 va = *(const float4*)&A[(size_t)(bm + ra) * K + k0 + ca];
            As[ca + 0][ra] = va.x;
            As[ca + 1][ra] = va.y;
            As[ca + 2][ra] = va.z;
            As[ca + 3][ra] = va.w;
            // W: 16 rows x 128 cols -> 512 float4
            int rb = idx >> 5;                  // row 0..15
            int cb = (idx & 31) << 2;           // col 0..124
            *(float4*)&Bs[rb][cb] = *(const float4*)&Wm[(size_t)(k0 + rb) * N + bn + cb];
        }
        __syncthreads();

#pragma unroll
        for (int kk = 0; kk < 16; kk++) {
            float4 a0 = *(float4*)&As[kk][ty * 8];
            float4 a1 = *(float4*)&As[kk][ty * 8 + 4];
            float4 b0 = *(float4*)&Bs[kk][tx * 8];
            float4 b1 = *(float4*)&Bs[kk][tx * 8 + 4];
            float ra[8] = {a0.x, a0.y, a0.z, a0.w, a1.x, a1.y, a1.z, a1.w};
            float rb[8] = {b0.x, b0.y, b0.z, b0.w, b1.x, b1.y, b1.z, b1.w};
#pragma unroll
            for (int i = 0; i < 8; i++)
#pragma unroll
                for (int j = 0; j < 8; j++)
                    acc[i][j] += ra[i] * rb[j];
        }
        __syncthreads();
    }

    float bz[8];
#pragma unroll
    for (int j = 0; j < 8; j++)
        bz[j] = bias ? bias[bn + tx * 8 + j] : 0.f;

#pragma unroll
    for (int i = 0; i < 8; i++) {
        size_t row = (size_t)(bm + ty * 8 + i) * N + bn + tx * 8;
#pragma unroll
        for (int j = 0; j < 8; j += 4) {
            float4 vw;
            vw.x = acc[i][j + 0] + bz[j + 0];
            vw.y = acc[i][j + 1] + bz[j + 1];
            vw.z = acc[i][j + 2] + bz[j + 2];
            vw.w = acc[i][j + 3] + bz[j + 3];
            *(float4*)&C[row + j] = vw;
        }
    }
}

// ---------------------------------------------------------------------------
// RoPE in-place on x[B*L, H*D]. One block per row; cos/sin table in smem.
// ---------------------------------------------------------------------------
__global__ void rope_kernel(float* __restrict__ x, int H)
{
    __shared__ float cs[64], sn[64];
    const int row = blockIdx.x;
    const int pos = row & (LL - 1);
    const int t = threadIdx.x;
    if (t < 64) {
        float e   = (float)(2 * t) * (1.0f / (float)DD);
        float inv = powf(1000000.0f, -e);
        float ang = (float)pos * inv;
        cs[t] = cosf(ang);
        sn[t] = sinf(ang);
    }
    __syncthreads();
    float* xr = x + (size_t)row * H * DD;
    for (int i = t; i < H * 64; i += blockDim.x) {
        int h = i >> 6;
        int d = i & 63;
        float x1 = xr[h * DD + d];
        float x2 = xr[h * DD + d + 64];
        float c = cs[d], s = sn[d];
        xr[h * DD + d]      = x1 * c - x2 * s;
        xr[h * DD + d + 64] = x2 * c + x1 * s;
    }
}

// ---------------------------------------------------------------------------
// Flash attention, causal, GQA (G=8). One block = one (b,h) x 64-query tile.
// 256 threads as (ty 0..15, tx 0..15).
//   S[64,64]: thread owns rows ty*4+r, cols tx+16*c (strided -> smem-friendly)
//   O[64,128]: thread owns rows ty*4+r, cols tx+16*c (c=0..7)
// ---------------------------------------------------------------------------
#define ATTN_SMEM_FLOATS (64*128 + 64*132 + 64*128 + 64*65)

__global__ __launch_bounds__(256) void attn_kernel(
    const float* __restrict__ q, const float* __restrict__ k,
    const float* __restrict__ v, float* __restrict__ o_out)
{
    extern __shared__ float sm[];
    float* Qs = sm;                       // [64][128]
    float* Ks = Qs + 64 * 128;            // [64][132]
    float* Vs = Ks + 64 * 132;            // [64][128]
    float* Ps = Vs + 64 * 128;            // [64][65]

    const int t  = threadIdx.x;
    const int ty = t >> 4;
    const int tx = t & 15;
    const int qt = blockIdx.x;            // 0..31
    const int bh = blockIdx.y;            // 0..31
    const int b  = bh >> 4;
    const int h  = bh & 15;
    const int hk = h >> 3;                // GQA group: 8 q heads per kv head
    const int q0 = qt * 64;

    // Load Q tile [64 x 128]
    {
        const float* qptr = q + ((size_t)(b * LL + q0)) * (HQ * DD) + h * DD;
        for (int i = t; i < 64 * 32; i += 256) {
            int r = i >> 5;
            int c = (i & 31) << 2;
            *(float4*)&Qs[r * 128 + c] = *(const float4*)&qptr[(size_t)r * (HQ * DD) + c];
        }
    }

    float m_[4], l_[4], o_[4][8];
#pragma unroll
    for (int r = 0; r < 4; r++) {
        m_[r] = -1e30f;
        l_[r] = 0.f;
#pragma unroll
        for (int c = 0; c < 8; c++) o_[r][c] = 0.f;
    }
    const float scale = 0.08838834764831845f;   // 1/sqrt(128)

    for (int kt = 0; kt <= qt; kt++) {
        __syncthreads();   // prior O-update done with Vs; Qs visible on first iter
        {
            const float* kptr = k + ((size_t)(b * LL + kt * 64)) * (HKV * DD) + hk * DD;
            const float* vptr = v + ((size_t)(b * LL + kt * 64)) * (HKV * DD) + hk * DD;
            for (int i = t; i < 64 * 32; i += 256) {
                int r = i >> 5;
                int c = (i & 31) << 2;
                *(float4*)&Ks[r * 132 + c] = *(const float4*)&kptr[(size_t)r * (HKV * DD) + c];
                *(float4*)&Vs[r * 128 + c] = *(const float4*)&vptr[(size_t)r * (HKV * DD) + c];
            }
        }
        __syncthreads();

        // S = Q @ K^T  (thread: 4 rows x 4 strided cols)
        float s_[4][4];
#pragma unroll
        for (int r = 0; r < 4; r++)
#pragma unroll
            for (int c = 0; c < 4; c++) s_[r][c] = 0.f;

#pragma unroll 4
        for (int k4 = 0; k4 < 32; k4++) {
            float4 ra[4], rb[4];
#pragma unroll
            for (int r = 0; r < 4; r++)
                ra[r] = *(float4*)&Qs[(ty * 4 + r) * 128 + k4 * 4];
#pragma unroll
            for (int c = 0; c < 4; c++)
                rb[c] = *(float4*)&Ks[(tx + 16 * c) * 132 + k4 * 4];
#pragma unroll
            for (int r = 0; r < 4; r++)
#pragma unroll
                for (int c = 0; c < 4; c++)
                    s_[r][c] += ra[r].x * rb[c].x + ra[r].y * rb[c].y +
                                ra[r].z * rb[c].z + ra[r].w * rb[c].w;
        }

        const bool diag = (kt == qt);
#pragma unroll
        for (int r = 0; r < 4; r++) {
            const int qi = q0 + ty * 4 + r;
            float mx = -1e30f;
#pragma unroll
            for (int c = 0; c < 4; c++) {
                int ki = kt * 64 + tx + 16 * c;
                float val = s_[r][c] * scale;
                if (diag && ki > qi) val = -1e30f;
                s_[r][c] = val;
                mx = fmaxf(mx, val);
            }
#pragma unroll
            for (int off = 8; off >= 1; off >>= 1)
                mx = fmaxf(mx, __shfl_xor_sync(0xffffffffu, mx, off));
            float mnew = fmaxf(m_[r], mx);
            float corr = __expf(m_[r] - mnew);
            float sum = 0.f;
#pragma unroll
            for (int c = 0; c < 4; c++) {
                float p = __expf(s_[r][c] - mnew);
                sum += p;
                Ps[(ty * 4 + r) * 65 + tx + 16 * c] = p;
            }
#pragma unroll
            for (int off = 8; off >= 1; off >>= 1)
                sum += __shfl_xor_sync(0xffffffffu, sum, off);
            l_[r] = l_[r] * corr + sum;
            m_[r] = mnew;
#pragma unroll
            for (int c = 0; c < 8; c++) o_[r][c] *= corr;
        }
        __syncthreads();

        // O += P @ V
#pragma unroll 4
        for (int kk = 0; kk < 64; kk++) {
            float pv[4];
#pragma unroll
            for (int r = 0; r < 4; r++)
                pv[r] = Ps[(ty * 4 + r) * 65 + kk];
#pragma unroll
            for (int c = 0; c < 8; c++) {
                float vv = Vs[kk * 128 + tx + 16 * c];
#pragma unroll
                for (int r = 0; r < 4; r++)
                    o_[r][c] += pv[r] * vv;
            }
        }
    }

    // Epilogue: O / l -> g_attn
#pragma unroll
    for (int r = 0; r < 4; r++) {
        float inv = 1.0f / l_[r];
        size_t rowoff = ((size_t)(b * LL + q0 + ty * 4 + r)) * (HQ * DD) + h * DD;
#pragma unroll
        for (int c = 0; c < 8; c++)
            o_out[rowoff + tx + 16 * c] = o_[r][c] * inv;
    }
}

// ---------------------------------------------------------------------------
// Launch
// ---------------------------------------------------------------------------
extern "C" void kernel_launch(void* const* d_in, const int* in_sizes, int n_in,
                              void* d_out, int out_size)
{
    const float* X  = (const float*)d_in[0];
    const float* Wq = (const float*)d_in[1];
    const float* bq = (const float*)d_in[2];
    const float* Wk = (const float*)d_in[3];
    const float* bk = (const float*)d_in[4];
    const float* Wv = (const float*)d_in[5];
    const float* bv = (const float*)d_in[6];
    const float* Wo = (const float*)d_in[7];
    float* out = (float*)d_out;

    float *qp, *kp, *vp, *ap;
    cudaGetSymbolAddress((void**)&qp, g_q);
    cudaGetSymbolAddress((void**)&kp, g_k);
    cudaGetSymbolAddress((void**)&vp, g_v);
    cudaGetSymbolAddress((void**)&ap, g_attn);

    // QKV projections
    sgemm_bias<<<dim3(EE / 128, MROWS / 128), 256>>>(X, Wq, bq, qp, MROWS, HQ * DD, EE);
    sgemm_bias<<<dim3((HKV * DD) / 128, MROWS / 128), 256>>>(X, Wk, bk, kp, MROWS, HKV * DD, EE);
    sgemm_bias<<<dim3((HKV * DD) / 128, MROWS / 128), 256>>>(X, Wv, bv, vp, MROWS, HKV * DD, EE);

    // RoPE
    rope_kernel<<<MROWS, 256>>>(qp, HQ);
    rope_kernel<<<MROWS, 256>>>(kp, HKV);

    // Attention
    const int attn_smem = ATTN_SMEM_FLOATS * (int)sizeof(float);
    cudaFuncSetAttribute(attn_kernel, cudaFuncAttributeMaxDynamicSharedMemorySize, attn_smem);
    attn_kernel<<<dim3(LL / 64, BB * HQ), 256, attn_smem>>>(qp, kp, vp, ap);

    // Output projection (no bias)
    sgemm_bias<<<dim3(EE / 128, MROWS / 128), 256>>>(ap, Wo, nullptr, out, MROWS, EE, EE);
}

// round 6
// speedup vs baseline: 1.5728x; 1.5728x over previous
#include <cuda_runtime.h>
#include <cuda_bf16.h>
#include <cstdint>
#include <cstddef>

// Problem constants
#define BB 2
#define LL 2048
#define EE 2048
#define HQ 16
#define HKV 2
#define DD 128
#define MROWS (BB*LL)   // 4096

// ---------------------------------------------------------------------------
// Scratch (device globals — no allocations allowed)
// ---------------------------------------------------------------------------
__device__ float g_q[(size_t)MROWS * HQ * DD];     // 32 MB
__device__ float g_k[(size_t)MROWS * HKV * DD];    // 4 MB
__device__ float g_v[(size_t)MROWS * HKV * DD];    // 4 MB
__device__ float g_attn[(size_t)MROWS * HQ * DD];  // 32 MB

// bf16 split activations (reused for X and for attn output)
__device__ __nv_bfloat16 g_ah[(size_t)MROWS * EE];
__device__ __nv_bfloat16 g_al[(size_t)MROWS * EE];
// bf16 split transposed weights [N, K] (K-major)
__device__ __nv_bfloat16 g_wqh[(size_t)(HQ*DD) * EE];
__device__ __nv_bfloat16 g_wql[(size_t)(HQ*DD) * EE];
__device__ __nv_bfloat16 g_wkh[(size_t)(HKV*DD) * EE];
__device__ __nv_bfloat16 g_wkl[(size_t)(HKV*DD) * EE];
__device__ __nv_bfloat16 g_wvh[(size_t)(HKV*DD) * EE];
__device__ __nv_bfloat16 g_wvl[(size_t)(HKV*DD) * EE];
__device__ __nv_bfloat16 g_woh[(size_t)EE * (HQ*DD)];
__device__ __nv_bfloat16 g_wol[(size_t)EE * (HQ*DD)];

// ---------------------------------------------------------------------------
// PTX helpers (base-ISA only: cp.async / ldmatrix / mma.sync — no tcgen05)
// ---------------------------------------------------------------------------
__device__ __forceinline__ uint32_t smem_u32(const void* p) {
    uint32_t a;
    asm("{ .reg .u64 t; cvta.to.shared.u64 t, %1; cvt.u32.u64 %0, t; }"
        : "=r"(a) : "l"(p));
    return a;
}

__device__ __forceinline__ void cpa16(uint32_t d, const void* s) {
    asm volatile("cp.async.cg.shared.global [%0], [%1], 16;" :: "r"(d), "l"(s));
}
#define CP_COMMIT() asm volatile("cp.async.commit_group;")
#define CP_WAIT(n)  asm volatile("cp.async.wait_group %0;" :: "n"(n))

__device__ __forceinline__ void ldmx4(uint32_t a, uint32_t r[4]) {
    asm volatile("ldmatrix.sync.aligned.m8n8.x4.shared.b16 {%0,%1,%2,%3}, [%4];"
                 : "=r"(r[0]), "=r"(r[1]), "=r"(r[2]), "=r"(r[3]) : "r"(a));
}
__device__ __forceinline__ void ldmx2(uint32_t a, uint32_t r[2]) {
    asm volatile("ldmatrix.sync.aligned.m8n8.x2.shared.b16 {%0,%1}, [%2];"
                 : "=r"(r[0]), "=r"(r[1]) : "r"(a));
}

__device__ __forceinline__ void mma16816(float c[4], const uint32_t a[4],
                                         const uint32_t b[2]) {
    asm volatile(
        "mma.sync.aligned.m16n8k16.row.col.f32.bf16.bf16.f32 "
        "{%0,%1,%2,%3}, {%4,%5,%6,%7}, {%8,%9}, {%0,%1,%2,%3};"
        : "+f"(c[0]), "+f"(c[1]), "+f"(c[2]), "+f"(c[3])
        : "r"(a[0]), "r"(a[1]), "r"(a[2]), "r"(a[3]), "r"(b[0]), "r"(b[1]));
}

// ---------------------------------------------------------------------------
// split: fp32 -> bf16 hi + bf16 lo (elementwise, vectorized)
// ---------------------------------------------------------------------------
__global__ void split_kernel(const float* __restrict__ x,
                             __nv_bfloat16* __restrict__ h,
                             __nv_bfloat16* __restrict__ l, int n4)
{
    int i = blockIdx.x * blockDim.x + threadIdx.x;
    if (i >= n4) return;
    float4 v = ((const float4*)x)[i];
    __nv_bfloat16 h0 = __float2bfloat16(v.x);
    __nv_bfloat16 h1 = __float2bfloat16(v.y);
    __nv_bfloat16 h2 = __float2bfloat16(v.z);
    __nv_bfloat16 h3 = __float2bfloat16(v.w);
    __nv_bfloat16 l0 = __float2bfloat16(v.x - __bfloat162float(h0));
    __nv_bfloat16 l1 = __float2bfloat16(v.y - __bfloat162float(h1));
    __nv_bfloat16 l2 = __float2bfloat16(v.z - __bfloat162float(h2));
    __nv_bfloat16 l3 = __float2bfloat16(v.w - __bfloat162float(h3));
    ((__nv_bfloat162*)h)[2*i]   = __halves2bfloat162(h0, h1);
    ((__nv_bfloat162*)h)[2*i+1] = __halves2bfloat162(h2, h3);
    ((__nv_bfloat162*)l)[2*i]   = __halves2bfloat162(l0, l1);
    ((__nv_bfloat162*)l)[2*i+1] = __halves2bfloat162(l2, l3);
}

// ---------------------------------------------------------------------------
// transpose+split: W[K,N] fp32 -> Th,Tl [N,K] bf16
// ---------------------------------------------------------------------------
__global__ void tsplit_kernel(const float* __restrict__ W,
                              __nv_bfloat16* __restrict__ Th,
                              __nv_bfloat16* __restrict__ Tl, int K, int N)
{
    __shared__ float ts[32][33];
    const int n0 = blockIdx.x * 32, k0 = blockIdx.y * 32;
    const int tx = threadIdx.x, ty = threadIdx.y;   // 32 x 8
    for (int i = ty; i < 32; i += 8)
        ts[i][tx] = W[(size_t)(k0 + i) * N + n0 + tx];
    __syncthreads();
    for (int i = ty; i < 32; i += 8) {
        float v = ts[tx][i];  // = W[k0+tx][n0+i]
        __nv_bfloat16 hv = __float2bfloat16(v);
        __nv_bfloat16 lv = __float2bfloat16(v - __bfloat162float(hv));
        size_t o = (size_t)(n0 + i) * K + k0 + tx;
        Th[o] = hv;
        Tl[o] = lv;
    }
}

// ---------------------------------------------------------------------------
// bf16x3 GEMM via mma.sync: C[M,N] = A @ B^T (+bias)
//   A given as Ahi/Alo [M,K] bf16 row-major
//   B given as Bhi/Blo [N,K] bf16 row-major (W pre-transposed)
// CTA tile 128x128, BK=32, 8 warps (2 x 4), warp tile 64x32, double-buffered
// cp.async. Smem rows padded to 40 bf16 (80 B) for conflict-free ldmatrix.
// ---------------------------------------------------------------------------
#define BKG 32
#define SROW 80                     // bytes per padded smem row
#define TBYTES (128 * SROW)         // 10240 per matrix tile
#define BUFBYTES (4 * TBYTES)       // Ah, Al, Bh, Bl
#define GSMEM_BYTES (2 * BUFBYTES)  // 81920

__device__ __forceinline__ void tile_cp(uint32_t sdst,
                                        const __nv_bfloat16* __restrict__ g,
                                        int ldk, int row0, int k0, int t)
{
    const char* gb = (const char*)(g + (size_t)row0 * ldk + k0);
    const size_t rs = (size_t)ldk * 2;
#pragma unroll
    for (int i = 0; i < 2; i++) {
        int idx = t + i * 256;          // 0..511
        int r = idx >> 2;               // row 0..127
        int c = (idx & 3) << 4;         // byte 0,16,32,48
        cpa16(sdst + r * SROW + c, gb + (size_t)r * rs + c);
    }
}

__global__ __launch_bounds__(256)
void gemm_bf16x3(const __nv_bfloat16* __restrict__ Ah,
                 const __nv_bfloat16* __restrict__ Al,
                 const __nv_bfloat16* __restrict__ Bh,
                 const __nv_bfloat16* __restrict__ Bl,
                 const float* __restrict__ bias,
                 float* __restrict__ C, int M, int N, int K)
{
    extern __shared__ char sm[];
    const uint32_t sbase = smem_u32(sm);
    const int t = threadIdx.x;
    const int wid = t >> 5, lane = t & 31;
    const int wm = wid & 1, wn = wid >> 1;       // 2 x 4 warp grid
    const int bm = blockIdx.y * 128, bn = blockIdx.x * 128;
    const int NT = K / BKG;

    float acc[4][4][4];
#pragma unroll
    for (int mt = 0; mt < 4; mt++)
#pragma unroll
        for (int nt = 0; nt < 4; nt++)
#pragma unroll
            for (int i = 0; i < 4; i++) acc[mt][nt][i] = 0.f;

    // Prologue: chunk 0 -> buffer 0
    {
        uint32_t s0 = sbase;
        tile_cp(s0,              Ah, K, bm, 0, t);
        tile_cp(s0 + TBYTES,     Al, K, bm, 0, t);
        tile_cp(s0 + 2 * TBYTES, Bh, K, bn, 0, t);
        tile_cp(s0 + 3 * TBYTES, Bl, K, bn, 0, t);
        CP_COMMIT();
    }

    // ldmatrix per-thread source addresses (within a tile)
    const int q = lane >> 3, r8 = lane & 7;
    const int arow = wm * 64 + (q & 1) * 8 + r8;
    const int acolb = ((q >> 1) * 8) * 2;            // byte offset of k-quad
    const int t16 = lane & 15;
    const int brow = wn * 32 + (t16 & 7);
    const int bcolb = ((t16 >> 3) * 8) * 2;

    for (int kt = 0; kt < NT; kt++) {
        const uint32_t sb = sbase + (kt & 1) * BUFBYTES;
        if (kt + 1 < NT) {
            const uint32_t sn = sbase + ((kt + 1) & 1) * BUFBYTES;
            const int k0 = (kt + 1) * BKG;
            tile_cp(sn,              Ah, K, bm, k0, t);
            tile_cp(sn + TBYTES,     Al, K, bm, k0, t);
            tile_cp(sn + 2 * TBYTES, Bh, K, bn, k0, t);
            tile_cp(sn + 3 * TBYTES, Bl, K, bn, k0, t);
            CP_COMMIT();
            CP_WAIT(1);
        } else {
            CP_WAIT(0);
        }
        __syncthreads();

#pragma unroll
        for (int kk = 0; kk < 2; kk++) {
            const uint32_t abase = sb + arow * SROW + kk * 32 + acolb;
            const uint32_t bbase = sb + 2 * TBYTES + brow * SROW + kk * 32 + bcolb;
            uint32_t ah_[4][4], al_[4][4], bh_[4][2], bl_[4][2];
#pragma unroll
            for (int mt = 0; mt < 4; mt++) {
                ldmx4(abase + mt * 16 * SROW, ah_[mt]);
                ldmx4(abase + TBYTES + mt * 16 * SROW, al_[mt]);
            }
#pragma unroll
            for (int nt = 0; nt < 4; nt++) {
                ldmx2(bbase + nt * 8 * SROW, bh_[nt]);
                ldmx2(bbase + TBYTES + nt * 8 * SROW, bl_[nt]);
            }
#pragma unroll
            for (int mt = 0; mt < 4; mt++)
#pragma unroll
                for (int nt = 0; nt < 4; nt++) {
                    mma16816(acc[mt][nt], ah_[mt], bh_[nt]);
                    mma16816(acc[mt][nt], ah_[mt], bl_[nt]);
                    mma16816(acc[mt][nt], al_[mt], bh_[nt]);
                }
        }
        __syncthreads();
    }

    // Epilogue: C fragment layout m16n8 f32: c0/c1 row gid col 2tid(+1); c2/c3 row gid+8
    const int gid = lane >> 2, tid2 = (lane & 3) * 2;
#pragma unroll
    for (int mt = 0; mt < 4; mt++) {
        const int row = bm + wm * 64 + mt * 16 + gid;
#pragma unroll
        for (int nt = 0; nt < 4; nt++) {
            const int col = bn + wn * 32 + nt * 8 + tid2;
            float b0 = 0.f, b1 = 0.f;
            if (bias) { b0 = bias[col]; b1 = bias[col + 1]; }
            float2 v0 = make_float2(acc[mt][nt][0] + b0, acc[mt][nt][1] + b1);
            float2 v1 = make_float2(acc[mt][nt][2] + b0, acc[mt][nt][3] + b1);
            *(float2*)&C[(size_t)row * N + col] = v0;
            *(float2*)&C[(size_t)(row + 8) * N + col] = v1;
        }
    }
}

// ---------------------------------------------------------------------------
// RoPE in-place on x[B*L, H*D]
// ---------------------------------------------------------------------------
__global__ void rope_kernel(float* __restrict__ x, int H)
{
    __shared__ float cs[64], sn[64];
    const int row = blockIdx.x;
    const int pos = row & (LL - 1);
    const int t = threadIdx.x;
    if (t < 64) {
        float e   = (float)(2 * t) * (1.0f / (float)DD);
        float inv = powf(1000000.0f, -e);
        float ang = (float)pos * inv;
        cs[t] = cosf(ang);
        sn[t] = sinf(ang);
    }
    __syncthreads();
    float* xr = x + (size_t)row * H * DD;
    for (int i = t; i < H * 64; i += blockDim.x) {
        int h = i >> 6;
        int d = i & 63;
        float x1 = xr[h * DD + d];
        float x2 = xr[h * DD + d + 64];
        float c = cs[d], s = sn[d];
        xr[h * DD + d]      = x1 * c - x2 * s;
        xr[h * DD + d + 64] = x2 * c + x1 * s;
    }
}

// ---------------------------------------------------------------------------
// Flash attention, causal, GQA (G=8). One block = one (b,h) x 64-query tile.
// ---------------------------------------------------------------------------
#define ATTN_SMEM_FLOATS (64*128 + 64*132 + 64*128 + 64*65)

__global__ __launch_bounds__(256) void attn_kernel(
    const float* __restrict__ q, const float* __restrict__ k,
    const float* __restrict__ v, float* __restrict__ o_out)
{
    extern __shared__ float smf[];
    float* Qs = smf;                      // [64][128]
    float* Ks = Qs + 64 * 128;            // [64][132]
    float* Vs = Ks + 64 * 132;            // [64][128]
    float* Ps = Vs + 64 * 128;            // [64][65]

    const int t  = threadIdx.x;
    const int ty = t >> 4;
    const int tx = t & 15;
    const int qt = blockIdx.x;
    const int bh = blockIdx.y;
    const int b  = bh >> 4;
    const int h  = bh & 15;
    const int hk = h >> 3;
    const int q0 = qt * 64;

    {
        const float* qptr = q + ((size_t)(b * LL + q0)) * (HQ * DD) + h * DD;
        for (int i = t; i < 64 * 32; i += 256) {
            int r = i >> 5;
            int c = (i & 31) << 2;
            *(float4*)&Qs[r * 128 + c] = *(const float4*)&qptr[(size_t)r * (HQ * DD) + c];
        }
    }

    float m_[4], l_[4], o_[4][8];
#pragma unroll
    for (int r = 0; r < 4; r++) {
        m_[r] = -1e30f;
        l_[r] = 0.f;
#pragma unroll
        for (int c = 0; c < 8; c++) o_[r][c] = 0.f;
    }
    const float scale = 0.08838834764831845f;

    for (int kt = 0; kt <= qt; kt++) {
        __syncthreads();
        {
            const float* kptr = k + ((size_t)(b * LL + kt * 64)) * (HKV * DD) + hk * DD;
            const float* vptr = v + ((size_t)(b * LL + kt * 64)) * (HKV * DD) + hk * DD;
            for (int i = t; i < 64 * 32; i += 256) {
                int r = i >> 5;
                int c = (i & 31) << 2;
                *(float4*)&Ks[r * 132 + c] = *(const float4*)&kptr[(size_t)r * (HKV * DD) + c];
                *(float4*)&Vs[r * 128 + c] = *(const float4*)&vptr[(size_t)r * (HKV * DD) + c];
            }
        }
        __syncthreads();

        float s_[4][4];
#pragma unroll
        for (int r = 0; r < 4; r++)
#pragma unroll
            for (int c = 0; c < 4; c++) s_[r][c] = 0.f;

#pragma unroll 4
        for (int k4 = 0; k4 < 32; k4++) {
            float4 ra[4], rb[4];
#pragma unroll
            for (int r = 0; r < 4; r++)
                ra[r] = *(float4*)&Qs[(ty * 4 + r) * 128 + k4 * 4];
#pragma unroll
            for (int c = 0; c < 4; c++)
                rb[c] = *(float4*)&Ks[(tx + 16 * c) * 132 + k4 * 4];
#pragma unroll
            for (int r = 0; r < 4; r++)
#pragma unroll
                for (int c = 0; c < 4; c++)
                    s_[r][c] += ra[r].x * rb[c].x + ra[r].y * rb[c].y +
                                ra[r].z * rb[c].z + ra[r].w * rb[c].w;
        }

        const bool diag = (kt == qt);
#pragma unroll
        for (int r = 0; r < 4; r++) {
            const int qi = q0 + ty * 4 + r;
            float mx = -1e30f;
#pragma unroll
            for (int c = 0; c < 4; c++) {
                int ki = kt * 64 + tx + 16 * c;
                float val = s_[r][c] * scale;
                if (diag && ki > qi) val = -1e30f;
                s_[r][c] = val;
                mx = fmaxf(mx, val);
            }
#pragma unroll
            for (int off = 8; off >= 1; off >>= 1)
                mx = fmaxf(mx, __shfl_xor_sync(0xffffffffu, mx, off));
            float mnew = fmaxf(m_[r], mx);
            float corr = __expf(m_[r] - mnew);
            float sum = 0.f;
#pragma unroll
            for (int c = 0; c < 4; c++) {
                float p = __expf(s_[r][c] - mnew);
                sum += p;
                Ps[(ty * 4 + r) * 65 + tx + 16 * c] = p;
            }
#pragma unroll
            for (int off = 8; off >= 1; off >>= 1)
                sum += __shfl_xor_sync(0xffffffffu, sum, off);
            l_[r] = l_[r] * corr + sum;
            m_[r] = mnew;
#pragma unroll
            for (int c = 0; c < 8; c++) o_[r][c] *= corr;
        }
        __syncthreads();

#pragma unroll 4
        for (int kk = 0; kk < 64; kk++) {
            float pv[4];
#pragma unroll
            for (int r = 0; r < 4; r++)
                pv[r] = Ps[(ty * 4 + r) * 65 + kk];
#pragma unroll
            for (int c = 0; c < 8; c++) {
                float vv = Vs[kk * 128 + tx + 16 * c];
#pragma unroll
                for (int r = 0; r < 4; r++)
                    o_[r][c] += pv[r] * vv;
            }
        }
    }

#pragma unroll
    for (int r = 0; r < 4; r++) {
        float inv = 1.0f / l_[r];
        size_t rowoff = ((size_t)(b * LL + q0 + ty * 4 + r)) * (HQ * DD) + h * DD;
#pragma unroll
        for (int c = 0; c < 8; c++)
            o_out[rowoff + tx + 16 * c] = o_[r][c] * inv;
    }
}

// ---------------------------------------------------------------------------
// Launch
// ---------------------------------------------------------------------------
extern "C" void kernel_launch(void* const* d_in, const int* in_sizes, int n_in,
                              void* d_out, int out_size)
{
    const float* X  = (const float*)d_in[0];
    const float* Wq = (const float*)d_in[1];
    const float* bq = (const float*)d_in[2];
    const float* Wk = (const float*)d_in[3];
    const float* bk = (const float*)d_in[4];
    const float* Wv = (const float*)d_in[5];
    const float* bv = (const float*)d_in[6];
    const float* Wo = (const float*)d_in[7];
    float* out = (float*)d_out;

    float *qp, *kp, *vp, *ap;
    __nv_bfloat16 *ah, *al, *wqh, *wql, *wkh, *wkl, *wvh, *wvl, *woh, *wol;
    cudaGetSymbolAddress((void**)&qp, g_q);
    cudaGetSymbolAddress((void**)&kp, g_k);
    cudaGetSymbolAddress((void**)&vp, g_v);
    cudaGetSymbolAddress((void**)&ap, g_attn);
    cudaGetSymbolAddress((void**)&ah, g_ah);
    cudaGetSymbolAddress((void**)&al, g_al);
    cudaGetSymbolAddress((void**)&wqh, g_wqh);
    cudaGetSymbolAddress((void**)&wql, g_wql);
    cudaGetSymbolAddress((void**)&wkh, g_wkh);
    cudaGetSymbolAddress((void**)&wkl, g_wkl);
    cudaGetSymbolAddress((void**)&wvh, g_wvh);
    cudaGetSymbolAddress((void**)&wvl, g_wvl);
    cudaGetSymbolAddress((void**)&woh, g_woh);
    cudaGetSymbolAddress((void**)&wol, g_wol);

    cudaFuncSetAttribute(gemm_bf16x3,
                         cudaFuncAttributeMaxDynamicSharedMemorySize, GSMEM_BYTES);

    const int n4 = (int)((size_t)MROWS * EE / 4);

    // Split activations + transpose/split weights
    split_kernel<<<(n4 + 255) / 256, 256>>>(X, ah, al, n4);
    tsplit_kernel<<<dim3((HQ*DD)/32, EE/32), dim3(32, 8)>>>(Wq, wqh, wql, EE, HQ*DD);
    tsplit_kernel<<<dim3((HKV*DD)/32, EE/32), dim3(32, 8)>>>(Wk, wkh, wkl, EE, HKV*DD);
    tsplit_kernel<<<dim3((HKV*DD)/32, EE/32), dim3(32, 8)>>>(Wv, wvh, wvl, EE, HKV*DD);
    tsplit_kernel<<<dim3(EE/32, (HQ*DD)/32), dim3(32, 8)>>>(Wo, woh, wol, HQ*DD, EE);

    // QKV projections (mma.sync bf16x3)
    gemm_bf16x3<<<dim3((HQ*DD)/128, MROWS/128), 256, GSMEM_BYTES>>>(
        ah, al, wqh, wql, bq, qp, MROWS, HQ*DD, EE);
    gemm_bf16x3<<<dim3((HKV*DD)/128, MROWS/128), 256, GSMEM_BYTES>>>(
        ah, al, wkh, wkl, bk, kp, MROWS, HKV*DD, EE);
    gemm_bf16x3<<<dim3((HKV*DD)/128, MROWS/128), 256, GSMEM_BYTES>>>(
        ah, al, wvh, wvl, bv, vp, MROWS, HKV*DD, EE);

    // RoPE
    rope_kernel<<<MROWS, 256>>>(qp, HQ);
    rope_kernel<<<MROWS, 256>>>(kp, HKV);

    // Attention (fp32 SIMT flash)
    const int attn_smem = ATTN_SMEM_FLOATS * (int)sizeof(float);
    cudaFuncSetAttribute(attn_kernel, cudaFuncAttributeMaxDynamicSharedMemorySize, attn_smem);
    attn_kernel<<<dim3(LL / 64, BB * HQ), 256, attn_smem>>>(qp, kp, vp, ap);

    // Output projection: split attn output, then GEMM (no bias)
    split_kernel<<<(n4 + 255) / 256, 256>>>(ap, ah, al, n4);
    gemm_bf16x3<<<dim3(EE/128, MROWS/128), 256, GSMEM_BYTES>>>(
        ah, al, woh, wol, nullptr, out, MROWS, EE, EE);
}

// round 7
// speedup vs baseline: 1.6244x; 1.0328x over previous
#include <cuda_runtime.h>
#include <cuda_bf16.h>
#include <cstdint>
#include <cstddef>

// Problem constants
#define BB 2
#define LL 2048
#define EE 2048
#define HQ 16
#define HKV 2
#define DD 128
#define MROWS (BB*LL)   // 4096

// ---------------------------------------------------------------------------
// Scratch (device globals — no allocations allowed)
// ---------------------------------------------------------------------------
__device__ float g_q[(size_t)MROWS * HQ * DD];     // 32 MB
__device__ float g_k[(size_t)MROWS * HKV * DD];    // 4 MB
__device__ float g_v[(size_t)MROWS * HKV * DD];    // 4 MB
__device__ float g_attn[(size_t)MROWS * HQ * DD];  // 32 MB

// bf16 split activations (reused for X and for attn output)
__device__ __nv_bfloat16 g_ah[(size_t)MROWS * EE];
__device__ __nv_bfloat16 g_al[(size_t)MROWS * EE];
// bf16 split transposed weights [N, K] (K-major)
__device__ __nv_bfloat16 g_wqh[(size_t)(HQ*DD) * EE];
__device__ __nv_bfloat16 g_wql[(size_t)(HQ*DD) * EE];
__device__ __nv_bfloat16 g_wkh[(size_t)(HKV*DD) * EE];
__device__ __nv_bfloat16 g_wkl[(size_t)(HKV*DD) * EE];
__device__ __nv_bfloat16 g_wvh[(size_t)(HKV*DD) * EE];
__device__ __nv_bfloat16 g_wvl[(size_t)(HKV*DD) * EE];
__device__ __nv_bfloat16 g_woh[(size_t)EE * (HQ*DD)];
__device__ __nv_bfloat16 g_wol[(size_t)EE * (HQ*DD)];

// ---------------------------------------------------------------------------
// PTX helpers (base-ISA only: cp.async / ldmatrix / mma.sync — no tcgen05)
// ---------------------------------------------------------------------------
__device__ __forceinline__ uint32_t smem_u32(const void* p) {
    uint32_t a;
    asm("{ .reg .u64 t; cvta.to.shared.u64 t, %1; cvt.u32.u64 %0, t; }"
        : "=r"(a) : "l"(p));
    return a;
}

__device__ __forceinline__ void cpa16(uint32_t d, const void* s) {
    asm volatile("cp.async.cg.shared.global [%0], [%1], 16;" :: "r"(d), "l"(s));
}
#define CP_COMMIT() asm volatile("cp.async.commit_group;")
#define CP_WAIT(n)  asm volatile("cp.async.wait_group %0;" :: "n"(n))

__device__ __forceinline__ void ldmx4(uint32_t a, uint32_t r[4]) {
    asm volatile("ldmatrix.sync.aligned.m8n8.x4.shared.b16 {%0,%1,%2,%3}, [%4];"
                 : "=r"(r[0]), "=r"(r[1]), "=r"(r[2]), "=r"(r[3]) : "r"(a));
}
__device__ __forceinline__ void ldmx2(uint32_t a, uint32_t r[2]) {
    asm volatile("ldmatrix.sync.aligned.m8n8.x2.shared.b16 {%0,%1}, [%2];"
                 : "=r"(r[0]), "=r"(r[1]) : "r"(a));
}

__device__ __forceinline__ void mma16816(float c[4], const uint32_t a[4],
                                         const uint32_t b[2]) {
    asm volatile(
        "mma.sync.aligned.m16n8k16.row.col.f32.bf16.bf16.f32 "
        "{%0,%1,%2,%3}, {%4,%5,%6,%7}, {%8,%9}, {%0,%1,%2,%3};"
        : "+f"(c[0]), "+f"(c[1]), "+f"(c[2]), "+f"(c[3])
        : "r"(a[0]), "r"(a[1]), "r"(a[2]), "r"(a[3]), "r"(b[0]), "r"(b[1]));
}

// ---------------------------------------------------------------------------
// split: fp32 -> bf16 hi + bf16 lo (elementwise, vectorized)
// ---------------------------------------------------------------------------
__global__ void split_kernel(const float* __restrict__ x,
                             __nv_bfloat16* __restrict__ h,
                             __nv_bfloat16* __restrict__ l, int n4)
{
    int i = blockIdx.x * blockDim.x + threadIdx.x;
    if (i >= n4) return;
    float4 v = ((const float4*)x)[i];
    __nv_bfloat16 h0 = __float2bfloat16(v.x);
    __nv_bfloat16 h1 = __float2bfloat16(v.y);
    __nv_bfloat16 h2 = __float2bfloat16(v.z);
    __nv_bfloat16 h3 = __float2bfloat16(v.w);
    __nv_bfloat16 l0 = __float2bfloat16(v.x - __bfloat162float(h0));
    __nv_bfloat16 l1 = __float2bfloat16(v.y - __bfloat162float(h1));
    __nv_bfloat16 l2 = __float2bfloat16(v.z - __bfloat162float(h2));
    __nv_bfloat16 l3 = __float2bfloat16(v.w - __bfloat162float(h3));
    ((__nv_bfloat162*)h)[2*i]   = __halves2bfloat162(h0, h1);
    ((__nv_bfloat162*)h)[2*i+1] = __halves2bfloat162(h2, h3);
    ((__nv_bfloat162*)l)[2*i]   = __halves2bfloat162(l0, l1);
    ((__nv_bfloat162*)l)[2*i+1] = __halves2bfloat162(l2, l3);
}

// ---------------------------------------------------------------------------
// transpose+split: W[K,N] fp32 -> Th,Tl [N,K] bf16
// ---------------------------------------------------------------------------
__global__ void tsplit_kernel(const float* __restrict__ W,
                              __nv_bfloat16* __restrict__ Th,
                              __nv_bfloat16* __restrict__ Tl, int K, int N)
{
    __shared__ float ts[32][33];
    const int n0 = blockIdx.x * 32, k0 = blockIdx.y * 32;
    const int tx = threadIdx.x, ty = threadIdx.y;   // 32 x 8
    for (int i = ty; i < 32; i += 8)
        ts[i][tx] = W[(size_t)(k0 + i) * N + n0 + tx];
    __syncthreads();
    for (int i = ty; i < 32; i += 8) {
        float v = ts[tx][i];  // = W[k0+tx][n0+i]
        __nv_bfloat16 hv = __float2bfloat16(v);
        __nv_bfloat16 lv = __float2bfloat16(v - __bfloat162float(hv));
        size_t o = (size_t)(n0 + i) * K + k0 + tx;
        Th[o] = hv;
        Tl[o] = lv;
    }
}

// ---------------------------------------------------------------------------
// bf16x3 GEMM via mma.sync: C[M,N] = A @ B^T (+bias)
//   A given as Ahi/Alo [M,K] bf16 row-major
//   B given as Bhi/Blo [N,K] bf16 row-major (W pre-transposed)
// CTA tile 128x128, BK=32, 8 warps (2 x 4), warp tile 64x32, double-buffered
// cp.async. Smem rows padded to 40 bf16 (80 B) for conflict-free ldmatrix.
// ---------------------------------------------------------------------------
#define BKG 32
#define SROW 80                     // bytes per padded smem row
#define TBYTES (128 * SROW)         // 10240 per matrix tile
#define BUFBYTES (4 * TBYTES)       // Ah, Al, Bh, Bl
#define GSMEM_BYTES (2 * BUFBYTES)  // 81920

__device__ __forceinline__ void tile_cp(uint32_t sdst,
                                        const __nv_bfloat16* __restrict__ g,
                                        int ldk, int row0, int k0, int t)
{
    const char* gb = (const char*)(g + (size_t)row0 * ldk + k0);
    const size_t rs = (size_t)ldk * 2;
#pragma unroll
    for (int i = 0; i < 2; i++) {
        int idx = t + i * 256;          // 0..511
        int r = idx >> 2;               // row 0..127
        int c = (idx & 3) << 4;         // byte 0,16,32,48
        cpa16(sdst + r * SROW + c, gb + (size_t)r * rs + c);
    }
}

__global__ __launch_bounds__(256)
void gemm_bf16x3(const __nv_bfloat16* __restrict__ Ah,
                 const __nv_bfloat16* __restrict__ Al,
                 const __nv_bfloat16* __restrict__ Bh,
                 const __nv_bfloat16* __restrict__ Bl,
                 const float* __restrict__ bias,
                 float* __restrict__ C, int M, int N, int K)
{
    extern __shared__ char sm[];
    const uint32_t sbase = smem_u32(sm);
    const int t = threadIdx.x;
    const int wid = t >> 5, lane = t & 31;
    const int wm = wid & 1, wn = wid >> 1;       // 2 x 4 warp grid
    const int bm = blockIdx.y * 128, bn = blockIdx.x * 128;
    const int NT = K / BKG;

    float acc[4][4][4];
#pragma unroll
    for (int mt = 0; mt < 4; mt++)
#pragma unroll
        for (int nt = 0; nt < 4; nt++)
#pragma unroll
            for (int i = 0; i < 4; i++) acc[mt][nt][i] = 0.f;

    // Prologue: chunk 0 -> buffer 0
    {
        uint32_t s0 = sbase;
        tile_cp(s0,              Ah, K, bm, 0, t);
        tile_cp(s0 + TBYTES,     Al, K, bm, 0, t);
        tile_cp(s0 + 2 * TBYTES, Bh, K, bn, 0, t);
        tile_cp(s0 + 3 * TBYTES, Bl, K, bn, 0, t);
        CP_COMMIT();
    }

    // ldmatrix per-thread source addresses (within a tile)
    const int q = lane >> 3, r8 = lane & 7;
    const int arow = wm * 64 + (q & 1) * 8 + r8;
    const int acolb = ((q >> 1) * 8) * 2;            // byte offset of k-quad
    const int t16 = lane & 15;
    const int brow = wn * 32 + (t16 & 7);
    const int bcolb = ((t16 >> 3) * 8) * 2;

    for (int kt = 0; kt < NT; kt++) {
        const uint32_t sb = sbase + (kt & 1) * BUFBYTES;
        if (kt + 1 < NT) {
            const uint32_t sn = sbase + ((kt + 1) & 1) * BUFBYTES;
            const int k0 = (kt + 1) * BKG;
            tile_cp(sn,              Ah, K, bm, k0, t);
            tile_cp(sn + TBYTES,     Al, K, bm, k0, t);
            tile_cp(sn + 2 * TBYTES, Bh, K, bn, k0, t);
            tile_cp(sn + 3 * TBYTES, Bl, K, bn, k0, t);
            CP_COMMIT();
            CP_WAIT(1);
        } else {
            CP_WAIT(0);
        }
        __syncthreads();

#pragma unroll
        for (int kk = 0; kk < 2; kk++) {
            const uint32_t abase = sb + arow * SROW + kk * 32 + acolb;
            const uint32_t bbase = sb + 2 * TBYTES + brow * SROW + kk * 32 + bcolb;
            uint32_t ah_[4][4], al_[4][4], bh_[4][2], bl_[4][2];
#pragma unroll
            for (int mt = 0; mt < 4; mt++) {
                ldmx4(abase + mt * 16 * SROW, ah_[mt]);
                ldmx4(abase + TBYTES + mt * 16 * SROW, al_[mt]);
            }
#pragma unroll
            for (int nt = 0; nt < 4; nt++) {
                ldmx2(bbase + nt * 8 * SROW, bh_[nt]);
                ldmx2(bbase + TBYTES + nt * 8 * SROW, bl_[nt]);
            }
#pragma unroll
            for (int mt = 0; mt < 4; mt++)
#pragma unroll
                for (int nt = 0; nt < 4; nt++) {
                    mma16816(acc[mt][nt], ah_[mt], bh_[nt]);
                    mma16816(acc[mt][nt], ah_[mt], bl_[nt]);
                    mma16816(acc[mt][nt], al_[mt], bh_[nt]);
                }
        }
        __syncthreads();
    }

    // Epilogue: C fragment layout m16n8 f32: c0/c1 row gid col 2tid(+1); c2/c3 row gid+8
    const int gid = lane >> 2, tid2 = (lane & 3) * 2;
#pragma unroll
    for (int mt = 0; mt < 4; mt++) {
        const int row = bm + wm * 64 + mt * 16 + gid;
#pragma unroll
        for (int nt = 0; nt < 4; nt++) {
            const int col = bn + wn * 32 + nt * 8 + tid2;
            float b0 = 0.f, b1 = 0.f;
            if (bias) { b0 = bias[col]; b1 = bias[col + 1]; }
            float2 v0 = make_float2(acc[mt][nt][0] + b0, acc[mt][nt][1] + b1);
            float2 v1 = make_float2(acc[mt][nt][2] + b0, acc[mt][nt][3] + b1);
            *(float2*)&C[(size_t)row * N + col] = v0;
            *(float2*)&C[(size_t)(row + 8) * N + col] = v1;
        }
    }
}

// ---------------------------------------------------------------------------
// RoPE in-place on x[B*L, H*D]
// ---------------------------------------------------------------------------
__global__ void rope_kernel(float* __restrict__ x, int H)
{
    __shared__ float cs[64], sn[64];
    const int row = blockIdx.x;
    const int pos = row & (LL - 1);
    const int t = threadIdx.x;
    if (t < 64) {
        float e   = (float)(2 * t) * (1.0f / (float)DD);
        float inv = powf(1000000.0f, -e);
        float ang = (float)pos * inv;
        cs[t] = cosf(ang);
        sn[t] = sinf(ang);
    }
    __syncthreads();
    float* xr = x + (size_t)row * H * DD;
    for (int i = t; i < H * 64; i += blockDim.x) {
        int h = i >> 6;
        int d = i & 63;
        float x1 = xr[h * DD + d];
        float x2 = xr[h * DD + d + 64];
        float c = cs[d], s = sn[d];
        xr[h * DD + d]      = x1 * c - x2 * s;
        xr[h * DD + d + 64] = x2 * c + x1 * s;
    }
}

// ---------------------------------------------------------------------------
// Flash attention, causal, GQA (G=8). One block = one (b,h) x 64-query tile.
// ---------------------------------------------------------------------------
#define ATTN_SMEM_FLOATS (64*128 + 64*132 + 64*128 + 64*65)

__global__ __launch_bounds__(256) void attn_kernel(
    const float* __restrict__ q, const float* __restrict__ k,
    const float* __restrict__ v, float* __restrict__ o_out)
{
    extern __shared__ float smf[];
    float* Qs = smf;                      // [64][128]
    float* Ks = Qs + 64 * 128;            // [64][132]
    float* Vs = Ks + 64 * 132;            // [64][128]
    float* Ps = Vs + 64 * 128;            // [64][65]

    const int t  = threadIdx.x;
    const int ty = t >> 4;
    const int tx = t & 15;
    const int qt = blockIdx.x;
    const int bh = blockIdx.y;
    const int b  = bh >> 4;
    const int h  = bh & 15;
    const int hk = h >> 3;
    const int q0 = qt * 64;

    {
        const float* qptr = q + ((size_t)(b * LL + q0)) * (HQ * DD) + h * DD;
        for (int i = t; i < 64 * 32; i += 256) {
            int r = i >> 5;
            int c = (i & 31) << 2;
            *(float4*)&Qs[r * 128 + c] = *(const float4*)&qptr[(size_t)r * (HQ * DD) + c];
        }
    }

    float m_[4], l_[4], o_[4][8];
#pragma unroll
    for (int r = 0; r < 4; r++) {
        m_[r] = -1e30f;
        l_[r] = 0.f;
#pragma unroll
        for (int c = 0; c < 8; c++) o_[r][c] = 0.f;
    }
    const float scale = 0.08838834764831845f;

    for (int kt = 0; kt <= qt; kt++) {
        __syncthreads();
        {
            const float* kptr = k + ((size_t)(b * LL + kt * 64)) * (HKV * DD) + hk * DD;
            const float* vptr = v + ((size_t)(b * LL + kt * 64)) * (HKV * DD) + hk * DD;
            for (int i = t; i < 64 * 32; i += 256) {
                int r = i >> 5;
                int c = (i & 31) << 2;
                *(float4*)&Ks[r * 132 + c] = *(const float4*)&kptr[(size_t)r * (HKV * DD) + c];
                *(float4*)&Vs[r * 128 + c] = *(const float4*)&vptr[(size_t)r * (HKV * DD) + c];
            }
        }
        __syncthreads();

        float s_[4][4];
#pragma unroll
        for (int r = 0; r < 4; r++)
#pragma unroll
            for (int c = 0; c < 4; c++) s_[r][c] = 0.f;

#pragma unroll 4
        for (int k4 = 0; k4 < 32; k4++) {
            float4 ra[4], rb[4];
#pragma unroll
            for (int r = 0; r < 4; r++)
                ra[r] = *(float4*)&Qs[(ty * 4 + r) * 128 + k4 * 4];
#pragma unroll
            for (int c = 0; c < 4; c++)
                rb[c] = *(float4*)&Ks[(tx + 16 * c) * 132 + k4 * 4];
#pragma unroll
            for (int r = 0; r < 4; r++)
#pragma unroll
                for (int c = 0; c < 4; c++)
                    s_[r][c] += ra[r].x * rb[c].x + ra[r].y * rb[c].y +
                                ra[r].z * rb[c].z + ra[r].w * rb[c].w;
        }

        const bool diag = (kt == qt);
#pragma unroll
        for (int r = 0; r < 4; r++) {
            const int qi = q0 + ty * 4 + r;
            float mx = -1e30f;
#pragma unroll
            for (int c = 0; c < 4; c++) {
                int ki = kt * 64 + tx + 16 * c;
                float val = s_[r][c] * scale;
                if (diag && ki > qi) val = -1e30f;
                s_[r][c] = val;
                mx = fmaxf(mx, val);
            }
#pragma unroll
            for (int off = 8; off >= 1; off >>= 1)
                mx = fmaxf(mx, __shfl_xor_sync(0xffffffffu, mx, off));
            float mnew = fmaxf(m_[r], mx);
            float corr = __expf(m_[r] - mnew);
            float sum = 0.f;
#pragma unroll
            for (int c = 0; c < 4; c++) {
                float p = __expf(s_[r][c] - mnew);
                sum += p;
                Ps[(ty * 4 + r) * 65 + tx + 16 * c] = p;
            }
#pragma unroll
            for (int off = 8; off >= 1; off >>= 1)
                sum += __shfl_xor_sync(0xffffffffu, sum, off);
            l_[r] = l_[r] * corr + sum;
            m_[r] = mnew;
#pragma unroll
            for (int c = 0; c < 8; c++) o_[r][c] *= corr;
        }
        __syncthreads();

#pragma unroll 4
        for (int kk = 0; kk < 64; kk++) {
            float pv[4];
#pragma unroll
            for (int r = 0; r < 4; r++)
                pv[r] = Ps[(ty * 4 + r) * 65 + kk];
#pragma unroll
            for (int c = 0; c < 8; c++) {
                float vv = Vs[kk * 128 + tx + 16 * c];
#pragma unroll
                for (int r = 0; r < 4; r++)
                    o_[r][c] += pv[r] * vv;
            }
        }
    }

#pragma unroll
    for (int r = 0; r < 4; r++) {
        float inv = 1.0f / l_[r];
        size_t rowoff = ((size_t)(b * LL + q0 + ty * 4 + r)) * (HQ * DD) + h * DD;
#pragma unroll
        for (int c = 0; c < 8; c++)
            o_out[rowoff + tx + 16 * c] = o_[r][c] * inv;
    }
}

// ---------------------------------------------------------------------------
// Launch
// ---------------------------------------------------------------------------
extern "C" void kernel_launch(void* const* d_in, const int* in_sizes, int n_in,
                              void* d_out, int out_size)
{
    const float* X  = (const float*)d_in[0];
    const float* Wq = (const float*)d_in[1];
    const float* bq = (const float*)d_in[2];
    const float* Wk = (const float*)d_in[3];
    const float* bk = (const float*)d_in[4];
    const float* Wv = (const float*)d_in[5];
    const float* bv = (const float*)d_in[6];
    const float* Wo = (const float*)d_in[7];
    float* out = (float*)d_out;

    float *qp, *kp, *vp, *ap;
    __nv_bfloat16 *ah, *al, *wqh, *wql, *wkh, *wkl, *wvh, *wvl, *woh, *wol;
    cudaGetSymbolAddress((void**)&qp, g_q);
    cudaGetSymbolAddress((void**)&kp, g_k);
    cudaGetSymbolAddress((void**)&vp, g_v);
    cudaGetSymbolAddress((void**)&ap, g_attn);
    cudaGetSymbolAddress((void**)&ah, g_ah);
    cudaGetSymbolAddress((void**)&al, g_al);
    cudaGetSymbolAddress((void**)&wqh, g_wqh);
    cudaGetSymbolAddress((void**)&wql, g_wql);
    cudaGetSymbolAddress((void**)&wkh, g_wkh);
    cudaGetSymbolAddress((void**)&wkl, g_wkl);
    cudaGetSymbolAddress((void**)&wvh, g_wvh);
    cudaGetSymbolAddress((void**)&wvl, g_wvl);
    cudaGetSymbolAddress((void**)&woh, g_woh);
    cudaGetSymbolAddress((void**)&wol, g_wol);

    cudaFuncSetAttribute(gemm_bf16x3,
                         cudaFuncAttributeMaxDynamicSharedMemorySize, GSMEM_BYTES);

    const int n4 = (int)((size_t)MROWS * EE / 4);

    // Split activations + transpose/split weights
    split_kernel<<<(n4 + 255) / 256, 256>>>(X, ah, al, n4);
    tsplit_kernel<<<dim3((HQ*DD)/32, EE/32), dim3(32, 8)>>>(Wq, wqh, wql, EE, HQ*DD);
    tsplit_kernel<<<dim3((HKV*DD)/32, EE/32), dim3(32, 8)>>>(Wk, wkh, wkl, EE, HKV*DD);
    tsplit_kernel<<<dim3((HKV*DD)/32, EE/32), dim3(32, 8)>>>(Wv, wvh, wvl, EE, HKV*DD);
    tsplit_kernel<<<dim3(EE/32, (HQ*DD)/32), dim3(32, 8)>>>(Wo, woh, wol, HQ*DD, EE);

    // QKV projections (mma.sync bf16x3)
    gemm_bf16x3<<<dim3((HQ*DD)/128, MROWS/128), 256, GSMEM_BYTES>>>(
        ah, al, wqh, wql, bq, qp, MROWS, HQ*DD, EE);
    gemm_bf16x3<<<dim3((HKV*DD)/128, MROWS/128), 256, GSMEM_BYTES>>>(
        ah, al, wkh, wkl, bk, kp, MROWS, HKV*DD, EE);
    gemm_bf16x3<<<dim3((HKV*DD)/128, MROWS/128), 256, GSMEM_BYTES>>>(
        ah, al, wvh, wvl, bv, vp, MROWS, HKV*DD, EE);

    // RoPE
    rope_kernel<<<MROWS, 256>>>(qp, HQ);
    rope_kernel<<<MROWS, 256>>>(kp, HKV);

    // Attention (fp32 SIMT flash)
    const int attn_smem = ATTN_SMEM_FLOATS * (int)sizeof(float);
    cudaFuncSetAttribute(attn_kernel, cudaFuncAttributeMaxDynamicSharedMemorySize, attn_smem);
    attn_kernel<<<dim3(LL / 64, BB * HQ), 256, attn_smem>>>(qp, kp, vp, ap);

    // Output projection: split attn output, then GEMM (no bias)
    split_kernel<<<(n4 + 255) / 256, 256>>>(ap, ah, al, n4);
    gemm_bf16x3<<<dim3(EE/128, MROWS/128), 256, GSMEM_BYTES>>>(
        ah, al, woh, wol, nullptr, out, MROWS, EE, EE);
}